// round 11
// baseline (speedup 1.0000x reference)
#include <cuda_runtime.h>
#include <cstddef>

#define BS 8
#define CLS 4
#define CCH 256
#define HW 16384
#define LL 19
#define TK 256
#define MH 64
#define MW 64

typedef unsigned long long u64;

// Scratch (device globals: allocation is forbidden)
__device__ float g_M[TK * CCH];       // M[k][c] = sum_t W2[t][k] * W1[t][c]
__device__ float g_W3T[TK * CCH];     // W3T[k][c] = W3[c][k]
__device__ float g_U[BS][LL][TK];     // (tok @ M) / 16
__device__ float g_t3[BS][LL][CCH];   // tok @ W3^T + b3
__device__ float g_a[BS][HW][20];     // softmaxed attn weights (19 used, padded)

// ---------------- f32x2 packed helpers (sm_103a) ----------------
__device__ __forceinline__ u64 pk2(float lo, float hi) {
    u64 r;
    asm("mov.b64 %0, {%1, %2};" : "=l"(r) : "f"(lo), "f"(hi));
    return r;
}
__device__ __forceinline__ void upk2(float& lo, float& hi, u64 v) {
    asm("mov.b64 {%0, %1}, %2;" : "=f"(lo), "=f"(hi) : "l"(v));
}
__device__ __forceinline__ u64 fma2(u64 a, u64 b, u64 c) {
    u64 d;
    asm("fma.rn.f32x2 %0, %1, %2, %3;" : "=l"(d) : "l"(a), "l"(b), "l"(c));
    return d;
}

// ---------------------------------------------------------------------------
// wprep: M[k][c] = sum_t W2[t][k]*W1[t][c]  and  W3T[k][c] = W3[c][k]
// ---------------------------------------------------------------------------
__global__ void __launch_bounds__(256) wprep_kernel(const float* __restrict__ W1,
                                                    const float* __restrict__ W2,
                                                    const float* __restrict__ W3) {
    int k0 = blockIdx.x * 4;
    int c = threadIdx.x;
    __shared__ float w2s[256][4];
    __shared__ float w3s[256][5];
    for (int i = threadIdx.x; i < 1024; i += 256) {
        int r = i >> 2, j = i & 3;
        w2s[r][j] = W2[r * TK + k0 + j];
        w3s[r][j] = W3[r * TK + k0 + j];
    }
    __syncthreads();

    float acc[4] = {0.f, 0.f, 0.f, 0.f};
#pragma unroll 8
    for (int t = 0; t < 256; t++) {
        float w1 = W1[t * CCH + c];
#pragma unroll
        for (int j = 0; j < 4; j++) acc[j] = fmaf(w2s[t][j], w1, acc[j]);
    }
#pragma unroll
    for (int j = 0; j < 4; j++) {
        g_M[(k0 + j) * CCH + c] = acc[j];
        g_W3T[(k0 + j) * CCH + c] = w3s[c][j];
    }
}

// ---------------------------------------------------------------------------
// tokprep: U[b][l][c] = (1/16) sum_k tok[b][l][k]*M[k][c]
//          t3[b][l][c] = sum_k tok[b][l][k]*W3T[k][c] + b3[c]
// ---------------------------------------------------------------------------
__global__ void __launch_bounds__(256) tokprep_kernel(const float* __restrict__ token_s,
                                                      const float* __restrict__ b3) {
    int b = blockIdx.x;
    int y = blockIdx.y;
    int phase = y / 5;
    int l0 = (y % 5) * 4;
    int lcnt = (l0 + 4 <= LL) ? 4 : (LL - l0);
    int c = threadIdx.x;

    __shared__ float tok[4][256];
    for (int i = threadIdx.x; i < 4 * 256; i += 256) {
        int l = i >> 8, k = i & 255;
        tok[l][k] = (l < lcnt) ? token_s[(b * LL + l0 + l) * TK + k] : 0.f;
    }
    __syncthreads();

    const float* Mp = phase ? g_W3T : g_M;
    float acc[4] = {0.f, 0.f, 0.f, 0.f};
#pragma unroll 8
    for (int k = 0; k < 256; k++) {
        float m = Mp[k * CCH + c];
#pragma unroll
        for (int l = 0; l < 4; l++) acc[l] = fmaf(tok[l][k], m, acc[l]);
    }
    if (phase == 0) {
        for (int l = 0; l < lcnt; l++) g_U[b][l0 + l][c] = acc[l] * 0.0625f;
    } else {
        float bias = b3[c];
        for (int l = 0; l < lcnt; l++) g_t3[b][l0 + l][c] = acc[l] + bias;
    }
}

// ---------------------------------------------------------------------------
// attn8: attn7 tiling + attn6 register double-buffer prefetch.
// Block = (group g of 2 batches, row-pair rp = 256 px = 128 pp).
// 16 chunks of 16 channels. fea for chunk kc+1 prefetched into 16 u64 regs
// right after the barrier, consumed at the next chunk's STS site; Phase B
// compute (~640 issue cycles) hides the load latency.
// Phase B: warp = (bsel, 5 l), thread = 4 pp; 4 X LDS.128 (conflict-free)
// + 5 U LDS.128 (broadcast) per 2-k step -> crossbar-light.
// grid = (4, 64), 256 threads. smem = 40 KB.
// ---------------------------------------------------------------------------
__global__ void __launch_bounds__(256, 2) attn8_kernel(const float* __restrict__ mask,
                                                       const float* __restrict__ fea) {
    __shared__ __align__(16) u64 arena[5120];   // 40960 B
    u64* Xs = arena;          // [2][16][128] : ((bsel*16)+ch)*128 + pp
    u64* Ud = arena + 4096;   // [2][20][16]  : ((bsel*20)+l)*16 + k

    int g = blockIdx.x;
    int rp = blockIdx.y;
    int b0 = (g & 1) * 4 + (g >> 1);  // {0,2},{4,6},{1,3},{5,7}
    int b1 = b0 + 2;
    int p = g >> 1;                    // src parity
    int tid = threadIdx.x;
    int w = tid >> 5, lane = tid & 31;
    int bsel = w & 1;
    int l0 = (w >> 1) * 5;             // 0,5,10,15 (l=19 zero pad)

    // Phase A geometry: thread owns pp-pair (2j, 2j+1), channels chb*4..+3
    int j = tid & 63;
    int chb = tid >> 6;
    int rA = j >> 5;
    int colj = j & 31;
    int rowA = rp * 2 + rA;
    int ppA = 2 * j;

    // mask -> duplicated-pair registers
    u64 md[2][4][2];
#pragma unroll
    for (int bi = 0; bi < 2; bi++) {
        int b = bi ? b1 : b0;
#pragma unroll
        for (int s = 0; s < 4; s++) {
            const float* mp = mask + ((size_t)(b * CLS + s) * MH + rp) * MW + 2 * colj;
            float m0 = 0.25f * mp[0];
            float m1 = 0.25f * mp[1];
            md[bi][s][0] = pk2(m0, m0);
            md[bi][s][1] = pk2(m1, m1);
        }
    }

    const float* fA[4];
#pragma unroll
    for (int s = 0; s < 4; s++)
        fA[s] = fea + (size_t)(4 * p + s) * CCH * HW + rowA * 128 + 4 * colj;

    // Ud staging job (tid < 160): (bi, l, k4); l==19 stores zeros
    int ujb = tid / 80;
    int ujrem = tid % 80;
    int ujl = ujrem >> 2, ujk = ujrem & 3;
    const float* ujsrc = 0;
    if (tid < 160 && ujl < LL) ujsrc = &g_U[ujb ? b1 : b0][ujl][ujk * 4];
    u64* udst = (tid < 160) ? &Ud[(ujb * 20 + ujl) * 16 + ujk * 4] : 0;

    u64 acc[5][4];
#pragma unroll
    for (int i = 0; i < 5; i++)
#pragma unroll
        for (int q = 0; q < 4; q++) acc[i][q] = 0ULL;

    int ppB = 2 * lane;

    // ---- prefetch chunk 0: fea (4 jj x 4 src as 2 u64 each -> 32 regs) + U ----
    ulonglong2 pf[4][4];
    float4 uq = make_float4(0.f, 0.f, 0.f, 0.f);
#pragma unroll
    for (int jj = 0; jj < 4; jj++) {
        size_t off = (size_t)(chb * 4 + jj) * HW;
#pragma unroll
        for (int s = 0; s < 4; s++) pf[jj][s] = *(const ulonglong2*)(fA[s] + off);
    }
    if (ujsrc) uq = *(const float4*)ujsrc;

    for (int kc = 0; kc < 16; kc++) {
        // ---- stage Ud from prefetched quad ----
        if (udst) {
            ulonglong2 s0, s1;
            s0.x = pk2(uq.x, uq.x); s0.y = pk2(uq.y, uq.y);
            s1.x = pk2(uq.z, uq.z); s1.y = pk2(uq.w, uq.w);
            ((ulonglong2*)udst)[0] = s0;
            ((ulonglong2*)udst)[1] = s1;
        }
        // ---- Phase A: combine prefetched fea -> Xs ----
#pragma unroll
        for (int jj = 0; jj < 4; jj++) {
            int ch = chb * 4 + jj;
            ulonglong2 F0 = pf[jj][0], F1 = pf[jj][1], F2 = pf[jj][2], F3 = pf[jj][3];
            ulonglong2 v0, v1;
            v0.x = fma2(md[0][3][0], F3.x, fma2(md[0][2][0], F2.x,
                   fma2(md[0][1][0], F1.x, fma2(md[0][0][0], F0.x, 0ULL))));
            v0.y = fma2(md[0][3][1], F3.y, fma2(md[0][2][1], F2.y,
                   fma2(md[0][1][1], F1.y, fma2(md[0][0][1], F0.y, 0ULL))));
            v1.x = fma2(md[1][3][0], F3.x, fma2(md[1][2][0], F2.x,
                   fma2(md[1][1][0], F1.x, fma2(md[1][0][0], F0.x, 0ULL))));
            v1.y = fma2(md[1][3][1], F3.y, fma2(md[1][2][1], F2.y,
                   fma2(md[1][1][1], F1.y, fma2(md[1][0][1], F0.y, 0ULL))));
            *(ulonglong2*)&Xs[ch * 128 + ppA] = v0;
            *(ulonglong2*)&Xs[(16 + ch) * 128 + ppA] = v1;
        }
        __syncthreads();

        // ---- issue prefetch for chunk kc+1 (hidden under Phase B) ----
        if (kc < 15) {
#pragma unroll
            for (int jj = 0; jj < 4; jj++) {
                size_t off = (size_t)((kc + 1) * 16 + chb * 4 + jj) * HW;
#pragma unroll
                for (int s = 0; s < 4; s++) pf[jj][s] = *(const ulonglong2*)(fA[s] + off);
            }
            if (ujsrc) uq = *(const float4*)(ujsrc + (kc + 1) * 16);
        }

        // ---- Phase B: 8 k-steps of 2 ----
        const u64* Xb = Xs + bsel * 2048;
        const u64* Ub = Ud + (bsel * 20 + l0) * 16;
#pragma unroll
        for (int ks = 0; ks < 8; ks++) {
            int k0 = ks * 2;
            ulonglong2 xa0 = *(const ulonglong2*)&Xb[k0 * 128 + ppB];
            ulonglong2 xa1 = *(const ulonglong2*)&Xb[k0 * 128 + 64 + ppB];
            ulonglong2 xb0 = *(const ulonglong2*)&Xb[(k0 + 1) * 128 + ppB];
            ulonglong2 xb1 = *(const ulonglong2*)&Xb[(k0 + 1) * 128 + 64 + ppB];
#pragma unroll
            for (int i = 0; i < 5; i++) {
                ulonglong2 u2 = *(const ulonglong2*)&Ub[i * 16 + k0];
                acc[i][0] = fma2(u2.x, xa0.x, acc[i][0]);
                acc[i][1] = fma2(u2.x, xa0.y, acc[i][1]);
                acc[i][2] = fma2(u2.x, xa1.x, acc[i][2]);
                acc[i][3] = fma2(u2.x, xa1.y, acc[i][3]);
                acc[i][0] = fma2(u2.y, xb0.x, acc[i][0]);
                acc[i][1] = fma2(u2.y, xb0.y, acc[i][1]);
                acc[i][2] = fma2(u2.y, xb1.x, acc[i][2]);
                acc[i][3] = fma2(u2.y, xb1.y, acc[i][3]);
            }
        }
        __syncthreads();
    }

    // ---- logits exchange (arena reuse): [2][20][128 pp] ----
    u64* Asm = arena;
#pragma unroll
    for (int i = 0; i < 5; i++) {
        ulonglong2 s0, s1;
        s0.x = acc[i][0]; s0.y = acc[i][1];
        s1.x = acc[i][2]; s1.y = acc[i][3];
        *(ulonglong2*)&Asm[(bsel * 20 + l0 + i) * 128 + ppB] = s0;
        *(ulonglong2*)&Asm[(bsel * 20 + l0 + i) * 128 + 64 + ppB] = s1;
    }
    __syncthreads();

    // ---- softmax: slot = (bq, px_local); 2 slots per thread ----
    const float* Af = (const float*)Asm;  // [2][20][256]
#pragma unroll
    for (int it = 0; it < 2; it++) {
        int slot = tid + it * 256;
        int bq = slot >> 8, px = slot & 255;
        int b = bq ? b1 : b0;
        float lg[LL];
#pragma unroll
        for (int l = 0; l < LL; l++) lg[l] = Af[(bq * 20 + l) * 256 + px];
        float mx = lg[0];
#pragma unroll
        for (int l = 1; l < LL; l++) mx = fmaxf(mx, lg[l]);
        float e[LL], sum = 0.f;
#pragma unroll
        for (int l = 0; l < LL; l++) { e[l] = __expf(lg[l] - mx); sum += e[l]; }
        float inv = 1.f / sum;
        float outv[20];
#pragma unroll
        for (int l = 0; l < LL; l++) outv[l] = (lg[l] != 0.f) ? e[l] * inv : 0.f;
        outv[19] = 0.f;
        float4* dst = (float4*)g_a[b][rp * 256 + px];
#pragma unroll
        for (int q = 0; q < 5; q++) dst[q] = ((float4*)outv)[q];
    }
}

// ---------------------------------------------------------------------------
// out8: out[b,c,n] = fea[b,c,n] + sum_l a[b,n,l] * t3[b,l,c]
// f32x2 lanes = (l, l+1) pairs; 2 px/thread (keeps regs ~70):
// per channel: 5 broadcast LDS.128 + 20 fma2 + LDG.64 + STG.64.
// grid = (BS, 64 px-tiles of 256, 2 c-halves), 128 threads.
// ---------------------------------------------------------------------------
__global__ void __launch_bounds__(128, 4) out8_kernel(const float* __restrict__ fea,
                                                      float* __restrict__ out) {
    int b = blockIdx.x;
    int c0 = blockIdx.z * 128;

    __shared__ __align__(16) u64 t3lp[128][10];  // [ch][l-pair], 10240 B
    {
        int ch = threadIdx.x;
        u64 tmp[10];
#pragma unroll
        for (int lp = 0; lp < 10; lp++) {
            float e = g_t3[b][2 * lp][c0 + ch];
            float o = (2 * lp + 1 < LL) ? g_t3[b][2 * lp + 1][c0 + ch] : 0.f;
            tmp[lp] = pk2(e, o);
        }
#pragma unroll
        for (int q = 0; q < 5; q++)
            ((ulonglong2*)&t3lp[ch][0])[q] = ((ulonglong2*)tmp)[q];
    }
    __syncthreads();

    int n0 = blockIdx.y * 256 + threadIdx.x * 2;

    // a weights: ap[px][lp] = (a[l], a[l+1]) — direct u64 loads (layout pairs)
    u64 ap[2][10];
#pragma unroll
    for (int px = 0; px < 2; px++) {
        const ulonglong2* pa = (const ulonglong2*)g_a[b][n0 + px];
#pragma unroll
        for (int q = 0; q < 5; q++) {
            ulonglong2 v = pa[q];
            ap[px][2 * q] = v.x;
            ap[px][2 * q + 1] = v.y;
        }
    }

    const float* fp = fea + (size_t)b * CCH * HW + (size_t)c0 * HW + n0;
    float* op = out + (size_t)b * CCH * HW + (size_t)c0 * HW + n0;

    float2 fv = *(const float2*)fp;
#pragma unroll 2
    for (int ch = 0; ch < 128; ch++) {
        float2 fnext;
        if (ch < 127) fnext = *(const float2*)(fp + (size_t)(ch + 1) * HW);
        u64 a0 = 0ULL, a1 = 0ULL;
#pragma unroll
        for (int q = 0; q < 5; q++) {
            ulonglong2 t = ((const ulonglong2*)&t3lp[ch][0])[q];  // broadcast LDS.128
            a0 = fma2(ap[0][2 * q], t.x, a0);
            a1 = fma2(ap[1][2 * q], t.x, a1);
            a0 = fma2(ap[0][2 * q + 1], t.y, a0);
            a1 = fma2(ap[1][2 * q + 1], t.y, a1);
        }
        float lo0, hi0, lo1, hi1;
        upk2(lo0, hi0, a0);
        upk2(lo1, hi1, a1);
        float2 ov;
        ov.x = fv.x + lo0 + hi0;
        ov.y = fv.y + lo1 + hi1;
        *(float2*)(op + (size_t)ch * HW) = ov;
        fv = fnext;
    }
}

extern "C" void kernel_launch(void* const* d_in, const int* in_sizes, int n_in,
                              void* d_out, int out_size) {
    const float* mask    = (const float*)d_in[0];
    const float* fea     = (const float*)d_in[1];
    const float* token_s = (const float*)d_in[2];
    const float* W1      = (const float*)d_in[3];
    const float* W2      = (const float*)d_in[4];
    const float* W3      = (const float*)d_in[5];
    const float* b3      = (const float*)d_in[6];
    float* out = (float*)d_out;

    wprep_kernel<<<64, 256>>>(W1, W2, W3);
    tokprep_kernel<<<dim3(BS, 10), 256>>>(token_s, b3);
    attn8_kernel<<<dim3(4, 64), 256>>>(mask, fea);
    out8_kernel<<<dim3(BS, 64, 2), 128>>>(fea, out);
}

// round 16
// speedup vs baseline: 1.2348x; 1.2348x over previous
#include <cuda_runtime.h>
#include <cstddef>

#define BS 8
#define CLS 4
#define CCH 256
#define HW 16384
#define LL 19
#define TK 256
#define MH 64
#define MW 64

typedef unsigned long long u64;

// Scratch (device globals: allocation is forbidden)
__device__ float g_M[TK * CCH];       // M[k][c] = sum_t W2[t][k] * W1[t][c]
__device__ float g_W3T[TK * CCH];     // W3T[k][c] = W3[c][k]
__device__ float g_U[BS][LL][TK];     // (tok @ M) / 16
__device__ float g_t3[BS][LL][CCH];   // tok @ W3^T + b3
__device__ float g_a[BS][HW][20];     // softmaxed attn weights (19 used, padded)

// ---------------- f32x2 packed helpers (sm_103a) ----------------
__device__ __forceinline__ u64 pk2(float lo, float hi) {
    u64 r;
    asm("mov.b64 %0, {%1, %2};" : "=l"(r) : "f"(lo), "f"(hi));
    return r;
}
__device__ __forceinline__ void upk2(float& lo, float& hi, u64 v) {
    asm("mov.b64 {%0, %1}, %2;" : "=f"(lo), "=f"(hi) : "l"(v));
}
__device__ __forceinline__ u64 fma2(u64 a, u64 b, u64 c) {
    u64 d;
    asm("fma.rn.f32x2 %0, %1, %2, %3;" : "=l"(d) : "l"(a), "l"(b), "l"(c));
    return d;
}

// ---------------------------------------------------------------------------
// wprep: M[k][c] = sum_t W2[t][k]*W1[t][c]  and  W3T[k][c] = W3[c][k]
// ---------------------------------------------------------------------------
__global__ void __launch_bounds__(256) wprep_kernel(const float* __restrict__ W1,
                                                    const float* __restrict__ W2,
                                                    const float* __restrict__ W3) {
    int k0 = blockIdx.x * 4;
    int c = threadIdx.x;
    __shared__ float w2s[256][4];
    __shared__ float w3s[256][5];
    for (int i = threadIdx.x; i < 1024; i += 256) {
        int r = i >> 2, j = i & 3;
        w2s[r][j] = W2[r * TK + k0 + j];
        w3s[r][j] = W3[r * TK + k0 + j];
    }
    __syncthreads();

    float acc[4] = {0.f, 0.f, 0.f, 0.f};
#pragma unroll 8
    for (int t = 0; t < 256; t++) {
        float w1 = W1[t * CCH + c];
#pragma unroll
        for (int j = 0; j < 4; j++) acc[j] = fmaf(w2s[t][j], w1, acc[j]);
    }
#pragma unroll
    for (int j = 0; j < 4; j++) {
        g_M[(k0 + j) * CCH + c] = acc[j];
        g_W3T[(k0 + j) * CCH + c] = w3s[c][j];
    }
}

// ---------------------------------------------------------------------------
// tokprep: U[b][l][c] = (1/16) sum_k tok[b][l][k]*M[k][c]
//          t3[b][l][c] = sum_k tok[b][l][k]*W3T[k][c] + b3[c]
// ---------------------------------------------------------------------------
__global__ void __launch_bounds__(256) tokprep_kernel(const float* __restrict__ token_s,
                                                      const float* __restrict__ b3) {
    int b = blockIdx.x;
    int y = blockIdx.y;
    int phase = y / 5;
    int l0 = (y % 5) * 4;
    int lcnt = (l0 + 4 <= LL) ? 4 : (LL - l0);
    int c = threadIdx.x;

    __shared__ float tok[4][256];
    for (int i = threadIdx.x; i < 4 * 256; i += 256) {
        int l = i >> 8, k = i & 255;
        tok[l][k] = (l < lcnt) ? token_s[(b * LL + l0 + l) * TK + k] : 0.f;
    }
    __syncthreads();

    const float* Mp = phase ? g_W3T : g_M;
    float acc[4] = {0.f, 0.f, 0.f, 0.f};
#pragma unroll 8
    for (int k = 0; k < 256; k++) {
        float m = Mp[k * CCH + c];
#pragma unroll
        for (int l = 0; l < 4; l++) acc[l] = fmaf(tok[l][k], m, acc[l]);
    }
    if (phase == 0) {
        for (int l = 0; l < lcnt; l++) g_U[b][l0 + l][c] = acc[l] * 0.0625f;
    } else {
        float bias = b3[c];
        for (int l = 0; l < lcnt; l++) g_t3[b][l0 + l][c] = acc[l] + bias;
    }
}

// ---------------------------------------------------------------------------
// attn7 (measured best, R10): LDS-minimized smem-tiled GEMM.
// Block = (group g of 2 batches, row-pair rp = 256 px = 128 pp).
// 16 chunks of 16 channels. Phase A: LDG.128 fea, mask-combine -> Xs.
// Phase B: warp = (bsel, 5 l), thread = 4 pp; conflict-free LDS.128 X +
// broadcast LDS.128 U; 9 LDS per 40 fma2.
// grid = (4, 64), 256 threads. smem = 40 KB, 2 blocks/SM -> 256 blocks = 1 wave.
// ---------------------------------------------------------------------------
__global__ void __launch_bounds__(256, 2) attn7_kernel(const float* __restrict__ mask,
                                                       const float* __restrict__ fea) {
    __shared__ __align__(16) u64 arena[5120];   // 40960 B
    u64* Xs = arena;          // [2][16][128] : ((bsel*16)+ch)*128 + pp
    u64* Ud = arena + 4096;   // [2][20][16]  : ((bsel*20)+l)*16 + k

    int g = blockIdx.x;
    int rp = blockIdx.y;
    int b0 = (g & 1) * 4 + (g >> 1);  // {0,2},{4,6},{1,3},{5,7}
    int b1 = b0 + 2;
    int p = g >> 1;                    // src parity
    int tid = threadIdx.x;
    int w = tid >> 5, lane = tid & 31;
    int bsel = w & 1;
    int l0 = (w >> 1) * 5;             // 0,5,10,15 (l=19 zero pad)

    // Phase A geometry: thread owns pp-pair (2j, 2j+1), channels chb*4..+3
    int j = tid & 63;
    int chb = tid >> 6;
    int rA = j >> 5;
    int colj = j & 31;
    int rowA = rp * 2 + rA;
    int ppA = 2 * j;

    // mask -> duplicated-pair registers (mi = (2rp+r)>>1 = rp for both rows)
    u64 md[2][4][2];
#pragma unroll
    for (int bi = 0; bi < 2; bi++) {
        int b = bi ? b1 : b0;
#pragma unroll
        for (int s = 0; s < 4; s++) {
            const float* mp = mask + ((size_t)(b * CLS + s) * MH + rp) * MW + 2 * colj;
            float m0 = 0.25f * mp[0];
            float m1 = 0.25f * mp[1];
            md[bi][s][0] = pk2(m0, m0);
            md[bi][s][1] = pk2(m1, m1);
        }
    }

    const float* fA0 = fea + (size_t)(4 * p + 0) * CCH * HW + rowA * 128 + 4 * colj;
    const float* fA1 = fea + (size_t)(4 * p + 1) * CCH * HW + rowA * 128 + 4 * colj;
    const float* fA2 = fea + (size_t)(4 * p + 2) * CCH * HW + rowA * 128 + 4 * colj;
    const float* fA3 = fea + (size_t)(4 * p + 3) * CCH * HW + rowA * 128 + 4 * colj;

    // Ud staging job (tid < 160): (bi, l, k4); l==19 stores zeros
    int ujb = tid / 80;
    int ujrem = tid % 80;
    int ujl = ujrem >> 2, ujk = ujrem & 3;
    const float* ujsrc = 0;
    if (tid < 160 && ujl < LL) ujsrc = &g_U[ujb ? b1 : b0][ujl][ujk * 4];
    u64* udst = (tid < 160) ? &Ud[(ujb * 20 + ujl) * 16 + ujk * 4] : 0;

    u64 acc[5][4];
#pragma unroll
    for (int i = 0; i < 5; i++)
#pragma unroll
        for (int q = 0; q < 4; q++) acc[i][q] = 0ULL;

    int ppB = 2 * lane;

    for (int kc = 0; kc < 16; kc++) {
        // ---- stage Ud ----
        if (udst) {
            float4 uq = make_float4(0.f, 0.f, 0.f, 0.f);
            if (ujsrc) uq = *(const float4*)(ujsrc + kc * 16);
            ulonglong2 s0, s1;
            s0.x = pk2(uq.x, uq.x); s0.y = pk2(uq.y, uq.y);
            s1.x = pk2(uq.z, uq.z); s1.y = pk2(uq.w, uq.w);
            ((ulonglong2*)udst)[0] = s0;
            ((ulonglong2*)udst)[1] = s1;
        }
        // ---- Phase A: 4 (ch, pp-pair) jobs, LDG.128 per source ----
#pragma unroll
        for (int jj = 0; jj < 4; jj++) {
            int ch = chb * 4 + jj;
            size_t off = (size_t)(kc * 16 + ch) * HW;
            ulonglong2 F0 = *(const ulonglong2*)(fA0 + off);
            ulonglong2 F1 = *(const ulonglong2*)(fA1 + off);
            ulonglong2 F2 = *(const ulonglong2*)(fA2 + off);
            ulonglong2 F3 = *(const ulonglong2*)(fA3 + off);
            ulonglong2 v0, v1;
            v0.x = fma2(md[0][3][0], F3.x, fma2(md[0][2][0], F2.x,
                   fma2(md[0][1][0], F1.x, fma2(md[0][0][0], F0.x, 0ULL))));
            v0.y = fma2(md[0][3][1], F3.y, fma2(md[0][2][1], F2.y,
                   fma2(md[0][1][1], F1.y, fma2(md[0][0][1], F0.y, 0ULL))));
            v1.x = fma2(md[1][3][0], F3.x, fma2(md[1][2][0], F2.x,
                   fma2(md[1][1][0], F1.x, fma2(md[1][0][0], F0.x, 0ULL))));
            v1.y = fma2(md[1][3][1], F3.y, fma2(md[1][2][1], F2.y,
                   fma2(md[1][1][1], F1.y, fma2(md[1][0][1], F0.y, 0ULL))));
            *(ulonglong2*)&Xs[ch * 128 + ppA] = v0;
            *(ulonglong2*)&Xs[(16 + ch) * 128 + ppA] = v1;
        }
        __syncthreads();

        // ---- Phase B: 8 k-steps of 2; 9 LDS per 40 fma2 ----
        const u64* Xb = Xs + bsel * 2048;
        const u64* Ub = Ud + (bsel * 20 + l0) * 16;
#pragma unroll
        for (int ks = 0; ks < 8; ks++) {
            int k0 = ks * 2;
            ulonglong2 xa0 = *(const ulonglong2*)&Xb[k0 * 128 + ppB];
            ulonglong2 xa1 = *(const ulonglong2*)&Xb[k0 * 128 + 64 + ppB];
            ulonglong2 xb0 = *(const ulonglong2*)&Xb[(k0 + 1) * 128 + ppB];
            ulonglong2 xb1 = *(const ulonglong2*)&Xb[(k0 + 1) * 128 + 64 + ppB];
#pragma unroll
            for (int i = 0; i < 5; i++) {
                ulonglong2 u2 = *(const ulonglong2*)&Ub[i * 16 + k0];
                acc[i][0] = fma2(u2.x, xa0.x, acc[i][0]);
                acc[i][1] = fma2(u2.x, xa0.y, acc[i][1]);
                acc[i][2] = fma2(u2.x, xa1.x, acc[i][2]);
                acc[i][3] = fma2(u2.x, xa1.y, acc[i][3]);
                acc[i][0] = fma2(u2.y, xb0.x, acc[i][0]);
                acc[i][1] = fma2(u2.y, xb0.y, acc[i][1]);
                acc[i][2] = fma2(u2.y, xb1.x, acc[i][2]);
                acc[i][3] = fma2(u2.y, xb1.y, acc[i][3]);
            }
        }
        __syncthreads();
    }

    // ---- logits exchange (arena reuse): [2][20][128 pp] ----
    u64* Asm = arena;
#pragma unroll
    for (int i = 0; i < 5; i++) {
        ulonglong2 s0, s1;
        s0.x = acc[i][0]; s0.y = acc[i][1];
        s1.x = acc[i][2]; s1.y = acc[i][3];
        *(ulonglong2*)&Asm[(bsel * 20 + l0 + i) * 128 + ppB] = s0;
        *(ulonglong2*)&Asm[(bsel * 20 + l0 + i) * 128 + 64 + ppB] = s1;
    }
    __syncthreads();

    // ---- softmax: slot = (bq, px_local); 2 slots per thread ----
    const float* Af = (const float*)Asm;  // [2][20][256]
#pragma unroll
    for (int it = 0; it < 2; it++) {
        int slot = tid + it * 256;
        int bq = slot >> 8, px = slot & 255;
        int b = bq ? b1 : b0;
        float lg[LL];
#pragma unroll
        for (int l = 0; l < LL; l++) lg[l] = Af[(bq * 20 + l) * 256 + px];
        float mx = lg[0];
#pragma unroll
        for (int l = 1; l < LL; l++) mx = fmaxf(mx, lg[l]);
        float e[LL], sum = 0.f;
#pragma unroll
        for (int l = 0; l < LL; l++) { e[l] = __expf(lg[l] - mx); sum += e[l]; }
        float inv = 1.f / sum;
        float outv[20];
#pragma unroll
        for (int l = 0; l < LL; l++) outv[l] = (lg[l] != 0.f) ? e[l] * inv : 0.f;
        outv[19] = 0.f;
        float4* dst = (float4*)g_a[b][rp * 256 + px];
#pragma unroll
        for (int q = 0; q < 5; q++) dst[q] = ((float4*)outv)[q];
    }
}

// ---------------------------------------------------------------------------
// out5 (measured best, R9): out[b,c,n] = fea[b,c,n] + sum_l a[b,n,l]*t3[b,l,c]
// 2 ADJACENT px per thread (one f32x2): a packed in 19 u64, t3 via
// broadcast LDS.128 (2 channels per access). LDG.64/STG.64 coalesced.
// grid = (BS, 64 px-tiles of 256, 2 c-halves of 128), 128 threads.
// ---------------------------------------------------------------------------
__global__ void __launch_bounds__(128) out5_kernel(const float* __restrict__ fea,
                                                   float* __restrict__ out) {
    int b = blockIdx.x;
    int c0 = blockIdx.z * 128;

    __shared__ u64 t3d[LL][128];  // duplicated pairs, 19456 B
    for (int idx = threadIdx.x; idx < LL * 128; idx += 128) {
        int l = idx >> 7, c = idx & 127;
        float v = g_t3[b][l][c0 + c];
        t3d[l][c] = pk2(v, v);
    }
    __syncthreads();

    int n0 = blockIdx.y * 256 + threadIdx.x * 2;  // 2 adjacent pixels

    // pack a: ap[l] = (a[n0][l], a[n0+1][l])
    u64 ap[LL];
    {
        const float4* pa0 = (const float4*)g_a[b][n0 + 0];
        const float4* pa1 = (const float4*)g_a[b][n0 + 1];
#pragma unroll
        for (int q = 0; q < 5; q++) {
            float4 qa = pa0[q], qb = pa1[q];
            int base = q * 4;
            if (base + 0 < LL) ap[base + 0] = pk2(qa.x, qb.x);
            if (base + 1 < LL) ap[base + 1] = pk2(qa.y, qb.y);
            if (base + 2 < LL) ap[base + 2] = pk2(qa.z, qb.z);
            if (base + 3 < LL) ap[base + 3] = pk2(qa.w, qb.w);
        }
    }

    const float* fp = fea + (size_t)b * CCH * HW + (size_t)c0 * HW + n0;
    float* op = out + (size_t)b * CCH * HW + (size_t)c0 * HW + n0;

#pragma unroll 4
    for (int c = 0; c < 128; c += 2) {
        size_t offA = (size_t)c * HW;
        size_t offB = offA + HW;
        u64 vA = *(const u64*)(fp + offA);  // init with fea (saves final add)
        u64 vB = *(const u64*)(fp + offB);
#pragma unroll
        for (int l = 0; l < LL; l++) {
            ulonglong2 t = *(const ulonglong2*)&t3d[l][c];  // LDS.128 broadcast
            vA = fma2(ap[l], t.x, vA);
            vB = fma2(ap[l], t.y, vB);
        }
        *(u64*)(op + offA) = vA;
        *(u64*)(op + offB) = vB;
    }
}

extern "C" void kernel_launch(void* const* d_in, const int* in_sizes, int n_in,
                              void* d_out, int out_size) {
    const float* mask    = (const float*)d_in[0];
    const float* fea     = (const float*)d_in[1];
    const float* token_s = (const float*)d_in[2];
    const float* W1      = (const float*)d_in[3];
    const float* W2      = (const float*)d_in[4];
    const float* W3      = (const float*)d_in[5];
    const float* b3      = (const float*)d_in[6];
    float* out = (float*)d_out;

    wprep_kernel<<<64, 256>>>(W1, W2, W3);
    tokprep_kernel<<<dim3(BS, 10), 256>>>(token_s, b3);
    attn7_kernel<<<dim3(4, 64), 256>>>(mask, fea);
    out5_kernel<<<dim3(BS, 64, 2), 128>>>(fea, out);
}